// round 15
// baseline (speedup 1.0000x reference)
#include <cuda_runtime.h>
#include <cuda_bf16.h>

typedef unsigned long long ull;

#define BATCH 64
#define SEQ   512
#define NIN   50
#define IK    200
#define HFC   1024
#define NOUT  128
#define HR    512
#define BS    (BATCH*SEQ)   // 32768

// ---------------- scratch (static device memory; no allocs) ----------------
__device__ float g_Z[(size_t)BS * IK];
__device__ float g_P[1048576];          // split-K partial slabs
__device__ float g_H1[NOUT * HFC];
__device__ float g_H2[NOUT * HFC];
__device__ float g_H3[NOUT * IK];
__device__ float g_W2[HR * IK];
__device__ float g_c1[HFC];
__device__ float g_c2[HFC];
__device__ float g_c3[NOUT];
__device__ float g_b2[HR];
__device__ float g_bp1[HR];
__device__ float g_pre0[(size_t)BS * HR];
__device__ float g_h0[(size_t)BS * HR];
__device__ float g_pre1[(size_t)BS * HR];

// ---------------- packed f32x2 helpers ----------------
__device__ __forceinline__ void ffma2(ull& c, ull a, ull b) {
    asm("fma.rn.f32x2 %0, %1, %2, %0;" : "+l"(c) : "l"(a), "l"(b));
}
__device__ __forceinline__ ull pack2(float x, float y) {
    ull r; asm("mov.b64 %0, {%1, %2};" : "=l"(r) : "f"(x), "f"(y)); return r;
}
__device__ __forceinline__ float2 unpack2(ull v) {
    float2 r; asm("mov.b64 {%0, %1}, %2;" : "=f"(r.x), "=f"(r.y) : "l"(v)); return r;
}
__device__ __forceinline__ unsigned smem_u32(const void* p) {
    unsigned a;
    asm("{ .reg .u64 t; cvta.to.shared.u64 t, %1; cvt.u32.u64 %0, t; }" : "=r"(a) : "l"(p));
    return a;
}
__device__ __forceinline__ float tanh_fast(float x) {
    float r; asm("tanh.approx.f32 %0, %1;" : "=f"(r) : "f"(x)); return r;
}
__device__ __forceinline__ void mbar_wait(unsigned addr, unsigned phase) {
    asm volatile(
        "{\n\t.reg .pred P;\n\t"
        "LAB_%=:\n\t"
        "mbarrier.try_wait.parity.acquire.cta.shared::cta.b64 P, [%0], %1, 0x989680;\n\t"
        "@P bra.uni DONE_%=;\n\t"
        "bra.uni LAB_%=;\n\t"
        "DONE_%=:\n\t}"
        :: "r"(addr), "r"(phase) : "memory");
}

// ---------------- fuzzy layer ----------------
__global__ void fuzzy_kernel(const float* __restrict__ x,
                             const float* __restrict__ fp,
                             float* __restrict__ Z) {
    int idx = blockIdx.x * blockDim.x + threadIdx.x;
    if (idx >= BS * IK) return;
    int bs = idx / IK;
    int c  = idx - bs * IK;
    int i  = c % NIN;
    float xv  = x[bs * NIN + i];
    float mu  = fp[2 * c];
    float sig = fp[2 * c + 1];
    float d = xv - mu;
    Z[idx] = expf(-(d * d) / sig);
}

// ---------------- split-K NN GEMM (partials, deterministic) ----------------
__global__ void __launch_bounds__(256, 2)
gemm_nn_sk(const float* __restrict__ A, const float* __restrict__ B,
           float* __restrict__ P, int M, int N, int K, int kslice) {
    __shared__ __align__(16) float As[16][36];
    __shared__ __align__(16) float Bs[16][68];
    const int tid = threadIdx.x;
    const int m0 = blockIdx.y * 32, n0 = blockIdx.x * 64;
    const int k0 = blockIdx.z * kslice, k1 = k0 + kslice;
    float* Cp = P + (size_t)blockIdx.z * M * N;
    const int tx = tid & 15, ty = tid >> 4;
    ull acc[2][2] = {{0ull, 0ull}, {0ull, 0ull}};

    for (int kt = k0; kt < k1; kt += 16) {
        if (tid < 128) {
            int ar = tid >> 2, ak = (tid & 3) * 4;
            float4 v = *(const float4*)(A + (size_t)(m0 + ar) * K + kt + ak);
            As[ak][ar] = v.x; As[ak + 1][ar] = v.y;
            As[ak + 2][ar] = v.z; As[ak + 3][ar] = v.w;
        }
        {
            int br = tid >> 4, bc = (tid & 15) * 4;
            int gn = n0 + bc;
            const float* bp = B + (size_t)(kt + br) * N;
            float4 v;
            if (gn + 3 < N) v = *(const float4*)(bp + gn);
            else {
                v.x = (gn     < N) ? bp[gn]     : 0.f;
                v.y = (gn + 1 < N) ? bp[gn + 1] : 0.f;
                v.z = (gn + 2 < N) ? bp[gn + 2] : 0.f;
                v.w = (gn + 3 < N) ? bp[gn + 3] : 0.f;
            }
            *(float4*)&Bs[br][bc] = v;
        }
        __syncthreads();
#pragma unroll
        for (int k = 0; k < 16; k++) {
            float2 a = *(const float2*)&As[k][ty * 2];
            ulonglong2 bv = *(const ulonglong2*)&Bs[k][tx * 4];
            ull a0 = pack2(a.x, a.x), a1 = pack2(a.y, a.y);
            ffma2(acc[0][0], a0, bv.x); ffma2(acc[0][1], a0, bv.y);
            ffma2(acc[1][0], a1, bv.x); ffma2(acc[1][1], a1, bv.y);
        }
        __syncthreads();
    }
#pragma unroll
    for (int i = 0; i < 2; i++) {
        int gm = m0 + ty * 2 + i;
#pragma unroll
        for (int p = 0; p < 2; p++) {
            float2 c2 = unpack2(acc[i][p]);
            int gn = n0 + tx * 4 + p * 2;
            if (gn < N)     Cp[(size_t)gm * N + gn]     = c2.x;
            if (gn + 1 < N) Cp[(size_t)gm * N + gn + 1] = c2.y;
        }
    }
}

__global__ void reduce_sk(const float* __restrict__ P, float* __restrict__ out,
                          int len, int sk) {
    int i = blockIdx.x * blockDim.x + threadIdx.x;
    if (i >= len) return;
    float s = 0.f;
    for (int z = 0; z < sk; z++) s += P[(size_t)z * len + i];
    out[i] = s;
}

// ---------------- warp-per-row vecmat: out = W@v (+b1+b2) ----------------
__global__ void vecmat_w(const float* __restrict__ W, const float* __restrict__ v,
                         const float* __restrict__ b1, const float* __restrict__ b2o,
                         float* __restrict__ out, int M, int K) {
    int warp = (blockIdx.x * blockDim.x + threadIdx.x) >> 5;
    int lane = threadIdx.x & 31;
    if (warp >= M) return;
    const float* wr = W + (size_t)warp * K;
    float s = 0.f;
    for (int k = lane * 4; k < K; k += 128) {
        float4 a = *(const float4*)(wr + k);
        float4 b = *(const float4*)(v + k);
        s += a.x * b.x + a.y * b.y + a.z * b.z + a.w * b.w;
    }
#pragma unroll
    for (int o = 16; o; o >>= 1) s += __shfl_xor_sync(~0u, s, o);
    if (lane == 0) {
        if (b1) s += b1[warp];
        if (b2o) s += b2o[warp];
        out[warp] = s;
    }
}

__global__ void add2(const float* __restrict__ a, const float* __restrict__ b,
                     float* __restrict__ o, int n) {
    int i = blockIdx.x * blockDim.x + threadIdx.x;
    if (i < n) o[i] = a[i] + b[i];
}

// ---------------- big fp32 GEMM: C = A[M,K] @ B[N,K]^T ----------
template<int BM, int BN, int BK, int TM, int TN, int NT>
__global__ void __launch_bounds__(NT, 2)
gemm_bt(const float* __restrict__ A, const float* __restrict__ B,
        float* __restrict__ C, int M, int N, int Kd) {
    __shared__ __align__(16) float As[BK][BM];
    __shared__ __align__(16) float Bs[BK][BN];
    const int tid = threadIdx.x;
    const int TX  = BN / TN;
    const int tx  = tid % TX;
    const int ty  = tid / TX;
    const int m0  = blockIdx.y * BM;
    const int n0  = blockIdx.x * BN;

    ull acc[TM][TN / 2];
#pragma unroll
    for (int i = 0; i < TM; i++)
#pragma unroll
        for (int j = 0; j < TN / 2; j++) acc[i][j] = 0ull;

    const int AKV = BK / 4;
    const int a_r = tid / AKV;
    const int a_k = (tid % AKV) * 4;
    const int AROWS = NT / AKV;

    const int kTiles = (Kd + BK - 1) / BK;
    for (int kt = 0; kt < kTiles; kt++) {
        const int k0 = kt * BK;
#pragma unroll
        for (int r = a_r; r < BM; r += AROWS) {
            float4 v = make_float4(0.f, 0.f, 0.f, 0.f);
            int gm = m0 + r, gk = k0 + a_k;
            if (gm < M && gk < Kd)
                v = *(const float4*)(A + (size_t)gm * Kd + gk);
            As[a_k + 0][r] = v.x; As[a_k + 1][r] = v.y;
            As[a_k + 2][r] = v.z; As[a_k + 3][r] = v.w;
        }
#pragma unroll
        for (int r = a_r; r < BN; r += AROWS) {
            float4 v = make_float4(0.f, 0.f, 0.f, 0.f);
            int gn = n0 + r, gk = k0 + a_k;
            if (gn < N && gk < Kd)
                v = *(const float4*)(B + (size_t)gn * Kd + gk);
            Bs[a_k + 0][r] = v.x; Bs[a_k + 1][r] = v.y;
            Bs[a_k + 2][r] = v.z; Bs[a_k + 3][r] = v.w;
        }
        __syncthreads();
#pragma unroll
        for (int k = 0; k < BK; k++) {
            float a[TM];
#pragma unroll
            for (int i = 0; i < TM; i += 4)
                *(float4*)&a[i] = *(const float4*)&As[k][ty * TM + i];
            ull bp[TN / 2];
#pragma unroll
            for (int j = 0; j < TN; j += 4) {
                ulonglong2 b2v = *(const ulonglong2*)&Bs[k][tx * TN + j];
                bp[j / 2]     = b2v.x;
                bp[j / 2 + 1] = b2v.y;
            }
#pragma unroll
            for (int i = 0; i < TM; i++) {
                ull ad = pack2(a[i], a[i]);
#pragma unroll
                for (int jp = 0; jp < TN / 2; jp++) ffma2(acc[i][jp], ad, bp[jp]);
            }
        }
        __syncthreads();
    }
#pragma unroll
    for (int i = 0; i < TM; i++) {
        int gm = m0 + ty * TM + i;
        if (gm >= M) continue;
#pragma unroll
        for (int jp = 0; jp < TN / 2; jp++) {
            float2 c2 = unpack2(acc[i][jp]);
            int gn = n0 + tx * TN + jp * 2;
            if (gn < N)     C[(size_t)gm * N + gn]     = c2.x;
            if (gn + 1 < N) C[(size_t)gm * N + gn + 1] = c2.y;
        }
    }
}

// ---------------- RNN recurrence: barrier-free shfl-reduce dataflow --------
// 16 clusters x 8 CTAs x 256 threads. CTA rank holds W rows [64*rank,+64).
// Lane layout: warp w, lane l: kc = l&7 (k-chunk of 64), row pair
// r0 = w*4 + (l>>3), r1 = r0+32. Cross-k reduction via 3x shfl.bfly inside
// the warp; NO __syncthreads in the step loop. Each lane finalizes exactly
// one (row,batch) output (index kc after butterfly) and pushes it b32 to
// all 8 CTAs' next h-buffer. Double-buffered mbarriers, expect_tx 8192B.
template<int NSTEPS>
__global__ void __cluster_dims__(8, 1, 1) __launch_bounds__(256, 1)
rnn_kernel(const float* __restrict__ pre, const float* __restrict__ Whh,
           const float* __restrict__ bias, float* __restrict__ hout) {
    __shared__ __align__(16) float hbuf[2][4][HR];   // 16 KB [buf][batch][col]
    __shared__ __align__(8) unsigned long long mbar[2];

    const int t = threadIdx.x;
    unsigned rank;
    asm("mov.u32 %0, %%cluster_ctarank;" : "=r"(rank));
    const int cid = blockIdx.x >> 3;
    const int lane = t & 31;
    const int w    = t >> 5;
    const int kc   = lane & 7;             // k-chunk
    const int r0   = w * 4 + (lane >> 3);  // local row 0..31
    // rows handled: r0 and r0+32; k range [kc*64, kc*64+64)

    ull wA[32], wB[32];
    {
        const ulonglong2* wq0 =
            (const ulonglong2*)(Whh + (size_t)(rank * 64 + r0) * HR + kc * 64);
        const ulonglong2* wq1 =
            (const ulonglong2*)(Whh + (size_t)(rank * 64 + r0 + 32) * HR + kc * 64);
#pragma unroll
        for (int i = 0; i < 16; i++) {
            ulonglong2 v0 = wq0[i];
            wA[2 * i] = v0.x; wA[2 * i + 1] = v0.y;
            ulonglong2 v1 = wq1[i];
            wB[2 * i] = v1.x; wB[2 * i + 1] = v1.y;
        }
    }

    // finalize identity: after butterfly, lane kc takes index kc = half*4+b
    const int fin_b   = kc & 3;
    const int fin_row = rank * 64 + r0 + (kc >> 2) * 32;   // global col 0..511
    const float bias_v = bias[fin_row];

    for (int i = t; i < 2 * 4 * HR; i += 256) ((float*)hbuf)[i] = 0.f;
    const unsigned hb0 = smem_u32(&hbuf[0][0][0]);
    const unsigned mb  = smem_u32(&mbar[0]);
    if (t == 0) {
        asm volatile("mbarrier.init.shared.b64 [%0], 1;" :: "r"(mb) : "memory");
        asm volatile("mbarrier.init.shared.b64 [%0], 1;" :: "r"(mb + 8) : "memory");
    }
    __syncthreads();
    asm volatile("barrier.cluster.arrive.aligned;" ::: "memory");
    asm volatile("barrier.cluster.wait.aligned;" ::: "memory");

    const int b0 = cid * 4;
    const size_t gidx0 = ((size_t)(b0 + fin_b) * SEQ) * HR + fin_row;
    const float* preP = pre + gidx0;
    float* houtP = hout + gidx0;

    unsigned peerM[8];
#pragma unroll
    for (int p = 0; p < 8; p++)
        asm("mapa.shared::cluster.u32 %0, %1, %2;" : "=r"(peerM[p]) : "r"(mb), "r"(p));
    const unsigned dH = hb0 - mb;                         // mbar -> hbuf delta
    const unsigned send_off = ((unsigned)fin_b * HR + fin_row) * 4u;

    unsigned ph0 = 0, ph1 = 0;
    for (int s = 0; s < NSTEPS; s++) {
        const int cur = s & 1, nxt = cur ^ 1;
        if (t == 0) {
            asm volatile("mbarrier.arrive.expect_tx.shared.b64 _, [%0], %1;"
                         :: "r"(mb + 8u * nxt), "r"(8192u) : "memory");
        }
        const float pv = preP[(size_t)s * HR];   // prefetch
        if (s > 0) {
            unsigned ph = cur ? ph1 : ph0;
            mbar_wait(mb + 8u * cur, ph);
            if (cur) ph1 ^= 1; else ph0 ^= 1;
        }
        // dots: p[half*4+b], half in {0,1} = rows r0, r0+32
        float pr[8];
#pragma unroll
        for (int b = 0; b < 4; b++) {
            const ulonglong2* hp = (const ulonglong2*)&hbuf[cur][b][kc * 64];
            ull a0 = 0ull, a1 = 0ull, c0 = 0ull, c1 = 0ull;
#pragma unroll
            for (int i = 0; i < 16; i++) {
                ulonglong2 h2 = hp[i];
                ffma2(a0, wA[2 * i], h2.x);
                ffma2(a1, wA[2 * i + 1], h2.y);
                ffma2(c0, wB[2 * i], h2.x);
                ffma2(c1, wB[2 * i + 1], h2.y);
            }
            float2 s0 = unpack2(a0), s1 = unpack2(a1);
            pr[b] = (s0.x + s0.y) + (s1.x + s1.y);
            float2 s2 = unpack2(c0), s3 = unpack2(c1);
            pr[4 + b] = (s2.x + s2.y) + (s3.x + s3.y);
        }
        // butterfly reduce over the 8 kc-lanes (warp-synchronous)
#pragma unroll
        for (int o = 1; o <= 4; o <<= 1) {
#pragma unroll
            for (int j = 0; j < 8; j++)
                pr[j] += __shfl_xor_sync(0xFFFFFFFFu, pr[j], o);
        }
        // select this lane's output: index == kc
        float m0 = (kc & 1) ? pr[1] : pr[0];
        float m1 = (kc & 1) ? pr[3] : pr[2];
        float m2 = (kc & 1) ? pr[5] : pr[4];
        float m3 = (kc & 1) ? pr[7] : pr[6];
        float n0v = (kc & 2) ? m1 : m0;
        float n1v = (kc & 2) ? m3 : m2;
        float v   = (kc & 4) ? n1v : n0v;
        float hn = tanh_fast(v + pv + bias_v);
        houtP[(size_t)s * HR] = hn;
        const unsigned hnb = __float_as_uint(hn);
        const unsigned doff = dH + (unsigned)nxt * 8192u + send_off;
        const unsigned moff = 8u * nxt;
#pragma unroll
        for (int p = 0; p < 8; p++) {
            asm volatile(
                "st.async.shared::cluster.mbarrier::complete_tx::bytes.b32 [%0], %1, [%2];"
                :: "r"(peerM[p] + doff), "r"(hnb), "r"(peerM[p] + moff) : "memory");
        }
    }
    asm volatile("barrier.cluster.arrive.aligned;" ::: "memory");
    asm volatile("barrier.cluster.wait.aligned;" ::: "memory");
}

// ---------------- host ----------------
extern "C" void kernel_launch(void* const* d_in, const int* in_sizes, int n_in,
                              void* d_out, int out_size) {
    const float* x     = (const float*)d_in[0];
    const float* fp    = (const float*)d_in[1];
    const float* fc0w  = (const float*)d_in[2];
    const float* fc0b  = (const float*)d_in[3];
    const float* fc1w  = (const float*)d_in[4];
    const float* fc1b  = (const float*)d_in[5];
    const float* fc2w  = (const float*)d_in[6];
    const float* fc2b  = (const float*)d_in[7];
    const float* fc3w  = (const float*)d_in[8];
    const float* fc3b  = (const float*)d_in[9];
    const float* wih0  = (const float*)d_in[10];
    const float* whh0  = (const float*)d_in[11];
    const float* bih0  = (const float*)d_in[12];
    const float* bhh0  = (const float*)d_in[13];
    const float* wih1  = (const float*)d_in[14];
    const float* whh1  = (const float*)d_in[15];
    const float* bih1  = (const float*)d_in[16];
    const float* bhh1  = (const float*)d_in[17];
    float* out = (float*)d_out;

    float *Z, *P, *H1, *H2, *H3, *W2, *c1, *c2, *c3, *b2, *bp1, *pre0, *h0, *pre1;
    cudaGetSymbolAddress((void**)&Z,    g_Z);
    cudaGetSymbolAddress((void**)&P,    g_P);
    cudaGetSymbolAddress((void**)&H1,   g_H1);
    cudaGetSymbolAddress((void**)&H2,   g_H2);
    cudaGetSymbolAddress((void**)&H3,   g_H3);
    cudaGetSymbolAddress((void**)&W2,   g_W2);
    cudaGetSymbolAddress((void**)&c1,   g_c1);
    cudaGetSymbolAddress((void**)&c2,   g_c2);
    cudaGetSymbolAddress((void**)&c3,   g_c3);
    cudaGetSymbolAddress((void**)&b2,   g_b2);
    cudaGetSymbolAddress((void**)&bp1,  g_bp1);
    cudaGetSymbolAddress((void**)&pre0, g_pre0);
    cudaGetSymbolAddress((void**)&h0,   g_h0);
    cudaGetSymbolAddress((void**)&pre1, g_pre1);

    // 0: fuzzy -> Z [32768,200]
    fuzzy_kernel<<<(BS * IK + 255) / 256, 256>>>(x, fp, Z);

    // 1-2: H1 = fc3w @ fc2w  [128,1024] K=1024, split-K 8
    gemm_nn_sk<<<dim3(16, 4, 8), 256>>>(fc3w, fc2w, P, NOUT, HFC, HFC, 128);
    reduce_sk<<<(NOUT * HFC + 255) / 256, 256>>>(P, H1, NOUT * HFC, 8);

    // 3: RNN probe (profiled slot) — 32 steps on zero-init pre0, scratch out
    rnn_kernel<32><<<128, 256>>>(pre0, whh0, b2, pre1);

    // 4-9: rest of compose chain
    gemm_nn_sk<<<dim3(16, 4, 8), 256>>>(H1, fc1w, P, NOUT, HFC, HFC, 128);
    reduce_sk<<<(NOUT * HFC + 255) / 256, 256>>>(P, H2, NOUT * HFC, 8);
    gemm_nn_sk<<<dim3(4, 4, 8), 256>>>(H2, fc0w, P, NOUT, IK, HFC, 128);
    reduce_sk<<<(NOUT * IK + 255) / 256, 256>>>(P, H3, NOUT * IK, 8);
    gemm_nn_sk<<<dim3(4, 16, 2), 256>>>(wih0, H3, P, HR, IK, NOUT, 64);
    reduce_sk<<<(HR * IK + 255) / 256, 256>>>(P, W2, HR * IK, 2);

    // 10-14: bias chain
    vecmat_w<<<(HFC * 32 + 255) / 256, 256>>>(fc1w, fc0b, fc1b, nullptr, c1, HFC, HFC);
    vecmat_w<<<(HFC * 32 + 255) / 256, 256>>>(fc2w, c1, fc2b, nullptr, c2, HFC, HFC);
    vecmat_w<<<(NOUT * 32 + 255) / 256, 256>>>(fc3w, c2, fc3b, nullptr, c3, NOUT, HFC);
    vecmat_w<<<(HR * 32 + 255) / 256, 256>>>(wih0, c3, bih0, bhh0, b2, HR, NOUT);
    add2<<<1, 512>>>(bih1, bhh1, bp1, HR);

    // 15: pre0 = Z @ W2^T  [32768,512] K=200
    gemm_bt<128, 128, 16, 8, 8, 256><<<dim3(HR / 128, BS / 128), 256>>>(Z, W2, pre0, BS, HR, IK);

    // 16: RNN layer 0
    rnn_kernel<SEQ><<<128, 256>>>(pre0, whh0, b2, h0);

    // 17: pre1 = h0 @ wih1^T  [32768,512] K=512
    gemm_bt<128, 128, 16, 8, 8, 256><<<dim3(HR / 128, BS / 128), 256>>>(h0, wih1, pre1, BS, HR, HR);

    // 18: RNN layer 1 -> out
    rnn_kernel<SEQ><<<128, 256>>>(pre1, whh1, bp1, out);
}

// round 16
// speedup vs baseline: 6.2860x; 6.2860x over previous
#include <cuda_runtime.h>
#include <cuda_bf16.h>

typedef unsigned long long ull;

#define BATCH 64
#define SEQ   512
#define NIN   50
#define IK    200
#define HFC   1024
#define NOUT  128
#define HR    512
#define BS    (BATCH*SEQ)   // 32768

// ---------------- scratch (static device memory; no allocs) ----------------
__device__ float g_Z[(size_t)BS * IK];
__device__ float g_P[1048576];          // split-K partial slabs
__device__ float g_H1[NOUT * HFC];
__device__ float g_H2[NOUT * HFC];
__device__ float g_H3[NOUT * IK];
__device__ float g_W2[HR * IK];
__device__ float g_c1[HFC];
__device__ float g_c2[HFC];
__device__ float g_c3[NOUT];
__device__ float g_b2[HR];
__device__ float g_bp1[HR];
__device__ float g_pre0[(size_t)BS * HR];
__device__ float g_h0[(size_t)BS * HR];
__device__ float g_pre1[(size_t)BS * HR];

// ---------------- packed f32x2 helpers ----------------
__device__ __forceinline__ void ffma2(ull& c, ull a, ull b) {
    asm("fma.rn.f32x2 %0, %1, %2, %0;" : "+l"(c) : "l"(a), "l"(b));
}
__device__ __forceinline__ ull pack2(float x, float y) {
    ull r; asm("mov.b64 %0, {%1, %2};" : "=l"(r) : "f"(x), "f"(y)); return r;
}
__device__ __forceinline__ float2 unpack2(ull v) {
    float2 r; asm("mov.b64 {%0, %1}, %2;" : "=f"(r.x), "=f"(r.y) : "l"(v)); return r;
}
__device__ __forceinline__ unsigned smem_u32(const void* p) {
    unsigned a;
    asm("{ .reg .u64 t; cvta.to.shared.u64 t, %1; cvt.u32.u64 %0, t; }" : "=r"(a) : "l"(p));
    return a;
}
__device__ __forceinline__ float tanh_fast(float x) {
    float r; asm("tanh.approx.f32 %0, %1;" : "=f"(r) : "f"(x)); return r;
}
__device__ __forceinline__ void mbar_wait(unsigned addr, unsigned phase) {
    asm volatile(
        "{\n\t.reg .pred P;\n\t"
        "LAB_%=:\n\t"
        "mbarrier.try_wait.parity.acquire.cta.shared::cta.b64 P, [%0], %1, 0x989680;\n\t"
        "@P bra.uni DONE_%=;\n\t"
        "bra.uni LAB_%=;\n\t"
        "DONE_%=:\n\t}"
        :: "r"(addr), "r"(phase) : "memory");
}

// ---------------- fuzzy layer ----------------
__global__ void fuzzy_kernel(const float* __restrict__ x,
                             const float* __restrict__ fp,
                             float* __restrict__ Z) {
    int idx = blockIdx.x * blockDim.x + threadIdx.x;
    if (idx >= BS * IK) return;
    int bs = idx / IK;
    int c  = idx - bs * IK;
    int i  = c % NIN;
    float xv  = x[bs * NIN + i];
    float mu  = fp[2 * c];
    float sig = fp[2 * c + 1];
    float d = xv - mu;
    Z[idx] = expf(-(d * d) / sig);
}

// ---------------- split-K NN GEMM (partials, deterministic) ----------------
__global__ void __launch_bounds__(256, 2)
gemm_nn_sk(const float* __restrict__ A, const float* __restrict__ B,
           float* __restrict__ P, int M, int N, int K, int kslice) {
    __shared__ __align__(16) float As[16][36];
    __shared__ __align__(16) float Bs[16][68];
    const int tid = threadIdx.x;
    const int m0 = blockIdx.y * 32, n0 = blockIdx.x * 64;
    const int k0 = blockIdx.z * kslice, k1 = k0 + kslice;
    float* Cp = P + (size_t)blockIdx.z * M * N;
    const int tx = tid & 15, ty = tid >> 4;
    ull acc[2][2] = {{0ull, 0ull}, {0ull, 0ull}};

    for (int kt = k0; kt < k1; kt += 16) {
        if (tid < 128) {
            int ar = tid >> 2, ak = (tid & 3) * 4;
            float4 v = *(const float4*)(A + (size_t)(m0 + ar) * K + kt + ak);
            As[ak][ar] = v.x; As[ak + 1][ar] = v.y;
            As[ak + 2][ar] = v.z; As[ak + 3][ar] = v.w;
        }
        {
            int br = tid >> 4, bc = (tid & 15) * 4;
            int gn = n0 + bc;
            const float* bp = B + (size_t)(kt + br) * N;
            float4 v;
            if (gn + 3 < N) v = *(const float4*)(bp + gn);
            else {
                v.x = (gn     < N) ? bp[gn]     : 0.f;
                v.y = (gn + 1 < N) ? bp[gn + 1] : 0.f;
                v.z = (gn + 2 < N) ? bp[gn + 2] : 0.f;
                v.w = (gn + 3 < N) ? bp[gn + 3] : 0.f;
            }
            *(float4*)&Bs[br][bc] = v;
        }
        __syncthreads();
#pragma unroll
        for (int k = 0; k < 16; k++) {
            float2 a = *(const float2*)&As[k][ty * 2];
            ulonglong2 bv = *(const ulonglong2*)&Bs[k][tx * 4];
            ull a0 = pack2(a.x, a.x), a1 = pack2(a.y, a.y);
            ffma2(acc[0][0], a0, bv.x); ffma2(acc[0][1], a0, bv.y);
            ffma2(acc[1][0], a1, bv.x); ffma2(acc[1][1], a1, bv.y);
        }
        __syncthreads();
    }
#pragma unroll
    for (int i = 0; i < 2; i++) {
        int gm = m0 + ty * 2 + i;
#pragma unroll
        for (int p = 0; p < 2; p++) {
            float2 c2 = unpack2(acc[i][p]);
            int gn = n0 + tx * 4 + p * 2;
            if (gn < N)     Cp[(size_t)gm * N + gn]     = c2.x;
            if (gn + 1 < N) Cp[(size_t)gm * N + gn + 1] = c2.y;
        }
    }
}

__global__ void reduce_sk(const float* __restrict__ P, float* __restrict__ out,
                          int len, int sk) {
    int i = blockIdx.x * blockDim.x + threadIdx.x;
    if (i >= len) return;
    float s = 0.f;
    for (int z = 0; z < sk; z++) s += P[(size_t)z * len + i];
    out[i] = s;
}

// ---------------- warp-per-row vecmat: out = W@v (+b1+b2) ----------------
__global__ void vecmat_w(const float* __restrict__ W, const float* __restrict__ v,
                         const float* __restrict__ b1, const float* __restrict__ b2o,
                         float* __restrict__ out, int M, int K) {
    int warp = (blockIdx.x * blockDim.x + threadIdx.x) >> 5;
    int lane = threadIdx.x & 31;
    if (warp >= M) return;
    const float* wr = W + (size_t)warp * K;
    float s = 0.f;
    for (int k = lane * 4; k < K; k += 128) {
        float4 a = *(const float4*)(wr + k);
        float4 b = *(const float4*)(v + k);
        s += a.x * b.x + a.y * b.y + a.z * b.z + a.w * b.w;
    }
#pragma unroll
    for (int o = 16; o; o >>= 1) s += __shfl_xor_sync(~0u, s, o);
    if (lane == 0) {
        if (b1) s += b1[warp];
        if (b2o) s += b2o[warp];
        out[warp] = s;
    }
}

__global__ void add2(const float* __restrict__ a, const float* __restrict__ b,
                     float* __restrict__ o, int n) {
    int i = blockIdx.x * blockDim.x + threadIdx.x;
    if (i < n) o[i] = a[i] + b[i];
}

// ---------------- big fp32 GEMM: C = A[M,K] @ B[N,K]^T ----------
template<int BM, int BN, int BK, int TM, int TN, int NT>
__global__ void __launch_bounds__(NT, 2)
gemm_bt(const float* __restrict__ A, const float* __restrict__ B,
        float* __restrict__ C, int M, int N, int Kd) {
    __shared__ __align__(16) float As[BK][BM];
    __shared__ __align__(16) float Bs[BK][BN];
    const int tid = threadIdx.x;
    const int TX  = BN / TN;
    const int tx  = tid % TX;
    const int ty  = tid / TX;
    const int m0  = blockIdx.y * BM;
    const int n0  = blockIdx.x * BN;

    ull acc[TM][TN / 2];
#pragma unroll
    for (int i = 0; i < TM; i++)
#pragma unroll
        for (int j = 0; j < TN / 2; j++) acc[i][j] = 0ull;

    const int AKV = BK / 4;
    const int a_r = tid / AKV;
    const int a_k = (tid % AKV) * 4;
    const int AROWS = NT / AKV;

    const int kTiles = (Kd + BK - 1) / BK;
    for (int kt = 0; kt < kTiles; kt++) {
        const int k0 = kt * BK;
#pragma unroll
        for (int r = a_r; r < BM; r += AROWS) {
            float4 v = make_float4(0.f, 0.f, 0.f, 0.f);
            int gm = m0 + r, gk = k0 + a_k;
            if (gm < M && gk < Kd)
                v = *(const float4*)(A + (size_t)gm * Kd + gk);
            As[a_k + 0][r] = v.x; As[a_k + 1][r] = v.y;
            As[a_k + 2][r] = v.z; As[a_k + 3][r] = v.w;
        }
#pragma unroll
        for (int r = a_r; r < BN; r += AROWS) {
            float4 v = make_float4(0.f, 0.f, 0.f, 0.f);
            int gn = n0 + r, gk = k0 + a_k;
            if (gn < N && gk < Kd)
                v = *(const float4*)(B + (size_t)gn * Kd + gk);
            Bs[a_k + 0][r] = v.x; Bs[a_k + 1][r] = v.y;
            Bs[a_k + 2][r] = v.z; Bs[a_k + 3][r] = v.w;
        }
        __syncthreads();
#pragma unroll
        for (int k = 0; k < BK; k++) {
            float a[TM];
#pragma unroll
            for (int i = 0; i < TM; i += 4)
                *(float4*)&a[i] = *(const float4*)&As[k][ty * TM + i];
            ull bp[TN / 2];
#pragma unroll
            for (int j = 0; j < TN; j += 4) {
                ulonglong2 b2v = *(const ulonglong2*)&Bs[k][tx * TN + j];
                bp[j / 2]     = b2v.x;
                bp[j / 2 + 1] = b2v.y;
            }
#pragma unroll
            for (int i = 0; i < TM; i++) {
                ull ad = pack2(a[i], a[i]);
#pragma unroll
                for (int jp = 0; jp < TN / 2; jp++) ffma2(acc[i][jp], ad, bp[jp]);
            }
        }
        __syncthreads();
    }
#pragma unroll
    for (int i = 0; i < TM; i++) {
        int gm = m0 + ty * TM + i;
        if (gm >= M) continue;
#pragma unroll
        for (int jp = 0; jp < TN / 2; jp++) {
            float2 c2 = unpack2(acc[i][jp]);
            int gn = n0 + tx * TN + jp * 2;
            if (gn < N)     C[(size_t)gm * N + gn]     = c2.x;
            if (gn + 1 < N) C[(size_t)gm * N + gn + 1] = c2.y;
        }
    }
}

// ---------------- RNN recurrence: 2-group pipelined dataflow ---------------
// (R12-validated config: 256 threads, 2 groups, b64 paired sends, approx tanh)
template<int NSTEPS>
__global__ void __cluster_dims__(8, 1, 1) __launch_bounds__(256, 1)
rnn_kernel(const float* __restrict__ pre, const float* __restrict__ Whh,
           const float* __restrict__ bias, float* __restrict__ hout) {
    __shared__ __align__(16) float hbufA[2][2][HR];  // 8 KB (buf, batch0-1, col)
    __shared__ __align__(16) float hbufB[2][2][HR];  // 8 KB (buf, batch2-3, col)
    __shared__ float red2[4][64][9];                 // padded, conflict-free
    __shared__ __align__(8) unsigned long long mbar[4];  // A0,A1,B0,B1

    const int t = threadIdx.x;
    unsigned rank;
    asm("mov.u32 %0, %%cluster_ctarank;" : "=r"(rank));
    const int cid = blockIdx.x >> 3;
    const int rc = t & 31;          // row-group (lane)
    const int kc = t >> 5;          // k-chunk == warp id (warp-uniform)

    // W rows (local rc, rc+32), k in [kc*64, +64), packed pairs (128 regs)
    ull wA[32], wB[32];
    {
        const ulonglong2* wq0 =
            (const ulonglong2*)(Whh + (size_t)(rank * 64 + rc) * HR + kc * 64);
        const ulonglong2* wq1 =
            (const ulonglong2*)(Whh + (size_t)(rank * 64 + rc + 32) * HR + kc * 64);
#pragma unroll
        for (int i = 0; i < 16; i++) {
            ulonglong2 v0 = wq0[i];
            wA[2 * i] = v0.x; wA[2 * i + 1] = v0.y;
            ulonglong2 v1 = wq1[i];
            wB[2 * i] = v1.x; wB[2 * i + 1] = v1.y;
        }
    }

    // finalize mapping: batch fbb = t>>6 (0..3), local col jl = t&63
    const int fbb = t >> 6;
    const int jl = t & 63;
    const float bias_v = bias[rank * 64 + jl];

    for (int i = t; i < 2 * 2 * HR; i += 256) {
        ((float*)hbufA)[i] = 0.f;
        ((float*)hbufB)[i] = 0.f;
    }
    const unsigned hA0 = smem_u32(&hbufA[0][0][0]);
    const unsigned hB0 = smem_u32(&hbufB[0][0][0]);
    const unsigned mb  = smem_u32(&mbar[0]);
    if (t == 0) {
#pragma unroll
        for (int q = 0; q < 4; q++)
            asm volatile("mbarrier.init.shared.b64 [%0], 1;" :: "r"(mb + 8u * q) : "memory");
    }
    __syncthreads();
    asm volatile("barrier.cluster.arrive.aligned;" ::: "memory");
    asm volatile("barrier.cluster.wait.aligned;" ::: "memory");

    const int b0 = cid * 4;
    const size_t gidx0 = ((size_t)(b0 + fbb) * SEQ) * HR + (size_t)rank * 64 + jl;
    const float* preP = pre + gidx0;
    float* houtP = hout + gidx0;

    unsigned peerA[8], peerB[8], peerM[8];
#pragma unroll
    for (int p = 0; p < 8; p++) {
        asm("mapa.shared::cluster.u32 %0, %1, %2;" : "=r"(peerA[p]) : "r"(hA0), "r"(p));
        asm("mapa.shared::cluster.u32 %0, %1, %2;" : "=r"(peerB[p]) : "r"(hB0), "r"(p));
        asm("mapa.shared::cluster.u32 %0, %1, %2;" : "=r"(peerM[p]) : "r"(mb), "r"(p));
    }
    // this thread's send offset (pair base) within a group buffer
    const unsigned send_off = (((unsigned)(fbb & 1) * HR) + rank * 64u + (jl & ~1)) * 4u;

    unsigned phA0 = 0, phA1 = 0, phB0 = 0, phB1 = 0;
    for (int s = 0; s < NSTEPS; s++) {
        const int cur = s & 1, nxt = cur ^ 1;
        if (t == 0) {
            asm volatile("mbarrier.arrive.expect_tx.shared.b64 _, [%0], %1;"
                         :: "r"(mb + 8u * nxt), "r"(4096u) : "memory");
            asm volatile("mbarrier.arrive.expect_tx.shared.b64 _, [%0], %1;"
                         :: "r"(mb + 16u + 8u * nxt), "r"(4096u) : "memory");
        }
        const float pv = preP[(size_t)s * HR];    // prefetch (own finalize slot)

        // ======== group A (batches 0,1) ========
        if (s > 0) {
            unsigned ph = cur ? phA1 : phA0;
            mbar_wait(mb + 8u * cur, ph);
            if (cur) phA1 ^= 1; else phA0 ^= 1;
        }
#pragma unroll
        for (int b = 0; b < 2; b++) {
            const ulonglong2* hp = (const ulonglong2*)&hbufA[cur][b][kc * 64];
            ull a0 = 0ull, a1 = 0ull, c0 = 0ull, c1 = 0ull;
#pragma unroll
            for (int i = 0; i < 16; i++) {
                ulonglong2 h2 = hp[i];
                ffma2(a0, wA[2 * i], h2.x);
                ffma2(a1, wA[2 * i + 1], h2.y);
                ffma2(c0, wB[2 * i], h2.x);
                ffma2(c1, wB[2 * i + 1], h2.y);
            }
            float2 s0 = unpack2(a0), s1 = unpack2(a1);
            red2[b][rc][kc] = (s0.x + s0.y) + (s1.x + s1.y);
            float2 s2 = unpack2(c0), s3 = unpack2(c1);
            red2[b][rc + 32][kc] = (s2.x + s2.y) + (s3.x + s3.y);
        }
        __syncthreads();
        if (fbb < 2) {
            float v = pv + bias_v;
#pragma unroll
            for (int k = 0; k < 8; k++) v += red2[fbb][jl][k];
            float hn = tanh_fast(v);
            houtP[(size_t)s * HR] = hn;
            float hi = __shfl_down_sync(0xFFFFFFFFu, hn, 1);
            if (!(t & 1)) {
                ull val = pack2(hn, hi);
                const unsigned doff = (unsigned)nxt * 4096u + send_off;
                const unsigned moff = 8u * nxt;
#pragma unroll
                for (int p = 0; p < 8; p++) {
                    asm volatile(
                        "st.async.shared::cluster.mbarrier::complete_tx::bytes.b64 [%0], %1, [%2];"
                        :: "r"(peerA[p] + doff), "l"(val), "r"(peerM[p] + moff) : "memory");
                }
            }
        }

        // ======== group B (batches 2,3) ========
        if (s > 0) {
            unsigned ph = cur ? phB1 : phB0;
            mbar_wait(mb + 16u + 8u * cur, ph);
            if (cur) phB1 ^= 1; else phB0 ^= 1;
        }
#pragma unroll
        for (int b = 0; b < 2; b++) {
            const ulonglong2* hp = (const ulonglong2*)&hbufB[cur][b][kc * 64];
            ull a0 = 0ull, a1 = 0ull, c0 = 0ull, c1 = 0ull;
#pragma unroll
            for (int i = 0; i < 16; i++) {
                ulonglong2 h2 = hp[i];
                ffma2(a0, wA[2 * i], h2.x);
                ffma2(a1, wA[2 * i + 1], h2.y);
                ffma2(c0, wB[2 * i], h2.x);
                ffma2(c1, wB[2 * i + 1], h2.y);
            }
            float2 s0 = unpack2(a0), s1 = unpack2(a1);
            red2[2 + b][rc][kc] = (s0.x + s0.y) + (s1.x + s1.y);
            float2 s2 = unpack2(c0), s3 = unpack2(c1);
            red2[2 + b][rc + 32][kc] = (s2.x + s2.y) + (s3.x + s3.y);
        }
        __syncthreads();
        if (fbb >= 2) {
            float v = pv + bias_v;
#pragma unroll
            for (int k = 0; k < 8; k++) v += red2[fbb][jl][k];
            float hn = tanh_fast(v);
            houtP[(size_t)s * HR] = hn;
            float hi = __shfl_down_sync(0xFFFFFFFFu, hn, 1);
            if (!(t & 1)) {
                ull val = pack2(hn, hi);
                const unsigned doff = (unsigned)nxt * 4096u + send_off;
                const unsigned moff = 16u + 8u * nxt;
#pragma unroll
                for (int p = 0; p < 8; p++) {
                    asm volatile(
                        "st.async.shared::cluster.mbarrier::complete_tx::bytes.b64 [%0], %1, [%2];"
                        :: "r"(peerB[p] + doff), "l"(val), "r"(peerM[p] + moff) : "memory");
                }
            }
        }
    }
    asm volatile("barrier.cluster.arrive.aligned;" ::: "memory");
    asm volatile("barrier.cluster.wait.aligned;" ::: "memory");
}

// ---------------- host ----------------
extern "C" void kernel_launch(void* const* d_in, const int* in_sizes, int n_in,
                              void* d_out, int out_size) {
    const float* x     = (const float*)d_in[0];
    const float* fp    = (const float*)d_in[1];
    const float* fc0w  = (const float*)d_in[2];
    const float* fc0b  = (const float*)d_in[3];
    const float* fc1w  = (const float*)d_in[4];
    const float* fc1b  = (const float*)d_in[5];
    const float* fc2w  = (const float*)d_in[6];
    const float* fc2b  = (const float*)d_in[7];
    const float* fc3w  = (const float*)d_in[8];
    const float* fc3b  = (const float*)d_in[9];
    const float* wih0  = (const float*)d_in[10];
    const float* whh0  = (const float*)d_in[11];
    const float* bih0  = (const float*)d_in[12];
    const float* bhh0  = (const float*)d_in[13];
    const float* wih1  = (const float*)d_in[14];
    const float* whh1  = (const float*)d_in[15];
    const float* bih1  = (const float*)d_in[16];
    const float* bhh1  = (const float*)d_in[17];
    float* out = (float*)d_out;

    float *Z, *P, *H1, *H2, *H3, *W2, *c1, *c2, *c3, *b2, *bp1, *pre0, *h0, *pre1;
    cudaGetSymbolAddress((void**)&Z,    g_Z);
    cudaGetSymbolAddress((void**)&P,    g_P);
    cudaGetSymbolAddress((void**)&H1,   g_H1);
    cudaGetSymbolAddress((void**)&H2,   g_H2);
    cudaGetSymbolAddress((void**)&H3,   g_H3);
    cudaGetSymbolAddress((void**)&W2,   g_W2);
    cudaGetSymbolAddress((void**)&c1,   g_c1);
    cudaGetSymbolAddress((void**)&c2,   g_c2);
    cudaGetSymbolAddress((void**)&c3,   g_c3);
    cudaGetSymbolAddress((void**)&b2,   g_b2);
    cudaGetSymbolAddress((void**)&bp1,  g_bp1);
    cudaGetSymbolAddress((void**)&pre0, g_pre0);
    cudaGetSymbolAddress((void**)&h0,   g_h0);
    cudaGetSymbolAddress((void**)&pre1, g_pre1);

    // 0: fuzzy -> Z [32768,200]
    fuzzy_kernel<<<(BS * IK + 255) / 256, 256>>>(x, fp, Z);

    // 1-8: compose chain W2 = wih0 @ fc3 @ fc2 @ fc1 @ fc0 (split-K + reduce)
    gemm_nn_sk<<<dim3(16, 4, 8), 256>>>(fc3w, fc2w, P, NOUT, HFC, HFC, 128);
    reduce_sk<<<(NOUT * HFC + 255) / 256, 256>>>(P, H1, NOUT * HFC, 8);
    gemm_nn_sk<<<dim3(16, 4, 8), 256>>>(H1, fc1w, P, NOUT, HFC, HFC, 128);
    reduce_sk<<<(NOUT * HFC + 255) / 256, 256>>>(P, H2, NOUT * HFC, 8);
    gemm_nn_sk<<<dim3(4, 4, 8), 256>>>(H2, fc0w, P, NOUT, IK, HFC, 128);
    reduce_sk<<<(NOUT * IK + 255) / 256, 256>>>(P, H3, NOUT * IK, 8);
    gemm_nn_sk<<<dim3(4, 16, 2), 256>>>(wih0, H3, P, HR, IK, NOUT, 64);
    reduce_sk<<<(HR * IK + 255) / 256, 256>>>(P, W2, HR * IK, 2);

    // 9-13: bias chain
    vecmat_w<<<(HFC * 32 + 255) / 256, 256>>>(fc1w, fc0b, fc1b, nullptr, c1, HFC, HFC);
    vecmat_w<<<(HFC * 32 + 255) / 256, 256>>>(fc2w, c1, fc2b, nullptr, c2, HFC, HFC);
    vecmat_w<<<(NOUT * 32 + 255) / 256, 256>>>(fc3w, c2, fc3b, nullptr, c3, NOUT, HFC);
    vecmat_w<<<(HR * 32 + 255) / 256, 256>>>(wih0, c3, bih0, bhh0, b2, HR, NOUT);
    add2<<<1, 512>>>(bih1, bhh1, bp1, HR);

    // 14: pre0 = Z @ W2^T  [32768,512] K=200
    gemm_bt<128, 128, 16, 8, 8, 256><<<dim3(HR / 128, BS / 128), 256>>>(Z, W2, pre0, BS, HR, IK);

    // 15: RNN layer 0
    rnn_kernel<SEQ><<<128, 256>>>(pre0, whh0, b2, h0);

    // 16: pre1 = h0 @ wih1^T  [32768,512] K=512
    gemm_bt<128, 128, 16, 8, 8, 256><<<dim3(HR / 128, BS / 128), 256>>>(h0, wih1, pre1, BS, HR, HR);

    // 17: RNN layer 1 -> out
    rnn_kernel<SEQ><<<128, 256>>>(pre1, whh1, bp1, out);
}